// round 7
// baseline (speedup 1.0000x reference)
#include <cuda_runtime.h>

// FeatureInteraction: B=16384, F=27, D=128
// out[b] = concat(embeddings[b].flatten() (3456), triu(E E^T, k=1) (351)) -> 3807 floats
//
// R7: vectorize the L1-instruction-bound streaming: LDG.128 (MLP=7 x 2 rounds)
//     + STS.128 into XOR-swizzled smem; flat output copied smem->gmem with
//     coalesced LDS.32/STG.32 (out rows are 4B-aligned only). Compute:
//     d-split warps, swizzled LDS.128, packed fma.rn.f32x2 (unchanged).

static constexpr int F      = 27;
static constexpr int F_PAD  = 28;
static constexpr int D      = 128;
static constexpr int HALF   = 64;
static constexpr int FLAT   = F * D;              // 3456
static constexpr int NPAIR  = (F * (F - 1)) / 2;  // 351
static constexpr int ROWLEN = FLAT + NPAIR;       // 3807
static constexpr int NBATCH = 3;                  // batch elements per block
static constexpr int THREADS = NBATCH * 2 * 32;   // 192

__device__ __forceinline__ unsigned long long pack2(float x, float y) {
    unsigned long long r;
    asm("mov.b64 %0, {%1, %2};" : "=l"(r) : "f"(x), "f"(y));
    return r;
}
__device__ __forceinline__ void unpack2(unsigned long long v, float& x, float& y) {
    asm("mov.b64 {%0, %1}, %2;" : "=f"(x), "=f"(y) : "l"(v));
}
__device__ __forceinline__ void ffma2(unsigned long long& acc,
                                      unsigned long long a, unsigned long long b) {
    asm("fma.rn.f32x2 %0, %1, %2, %0;" : "+l"(acc) : "l"(a), "l"(b));
}

// Row f = words [f*128, f*128+128); 16B chunk c stored at slot c ^ (f>>2).
__device__ __forceinline__ int sm_word(int f, int d) {
    return f * D + ((((d >> 2) ^ (f >> 2)) << 2) | (d & 3));
}

__global__ void __launch_bounds__(THREADS, 4)
fi_kernel(const float* __restrict__ in, float* __restrict__ out, int batch)
{
    __shared__ float sm[NBATCH * F_PAD * D];      // 43008 B

    const int tid  = threadIdx.x;
    const int warp = tid >> 5;
    const int lane = tid & 31;
    const int nb   = warp >> 1;                   // batch slot in block
    const int dh   = warp & 1;                    // d-half owned by this warp
    const int b    = blockIdx.x * NBATCH + nb;
    const bool valid = b < batch;

    const float* __restrict__ inb  = in  + (size_t)b * FLAT;
    float*       __restrict__ outb = out + (size_t)b * ROWLEN;
    float* smb = sm + nb * (F_PAD * D);

    // ---- Stage this warp's d-half of all rows: LDG.128 batches + STS.128 ----
    // lane group g = lane>>4 handles rows of parity g; chunk cq is this lane's
    // 16B column. Two rounds of 7 independent LDG.128 (MLP=7). Round B's
    // predicated f==27 lane writes zeros -> pad row initialized for free.
    if (valid) {
        const int g  = lane >> 4;
        const int cq = (lane & 15) + dh * 16;     // chunk 0..31 within row
        const float4* inb4 = reinterpret_cast<const float4*>(inb);

        #pragma unroll
        for (int round = 0; round < 2; ++round) {
            const int base = round * 14;
            float4 v[7];
            #pragma unroll
            for (int k = 0; k < 7; ++k) {
                const int f = base + 2 * k + g;
                v[k] = (f < F) ? inb4[f * 32 + cq]
                               : make_float4(0.f, 0.f, 0.f, 0.f);
            }
            #pragma unroll
            for (int k = 0; k < 7; ++k) {
                const int f = base + 2 * k + g;   // <= 27 = pad row
                *reinterpret_cast<float4*>(smb + f * D + ((cq ^ (f >> 2)) << 2)) = v[k];
            }
        }
    }
    __syncwarp();

    // ---- Flat output: coalesced smem readback -> coalesced STG.32 ----
    // (out rows are 4B-aligned only; vector STG impossible.)
    if (valid) {
        #pragma unroll 6
        for (int it = 0; it < F * 2; ++it) {      // 54 iters: this warp's d-half
            const int f = it >> 1;
            const int d = dh * HALF + ((it & 1) << 5) + lane;
            outb[f * D + d] = smb[sm_word(f, d)];
        }
    }

    // ---- Partial gram over this warp's d-half: lane<28 owns a 4x4 tile ----
    int ti = 0, tj = 0;
    float val[4][4];
    if (valid && lane < 28) {
        int l = lane, cnt = 7;
        while (l >= cnt) { l -= cnt; ++ti; --cnt; }
        tj = ti + l;

        unsigned long long acc[4][4];
        #pragma unroll
        for (int r = 0; r < 4; ++r)
            #pragma unroll
            for (int c = 0; c < 4; ++c) acc[r][c] = 0ull;

        const float* pi = smb + (4 * ti) * D;
        const float* pj = smb + (4 * tj) * D;

        const int c0 = dh * 16;
        #pragma unroll 2
        for (int c = c0; c < c0 + 16; ++c) {
            const int ci = (c ^ ti) << 2;
            const int cj = (c ^ tj) << 2;
            float4 ai4[4], aj4[4];
            #pragma unroll
            for (int r = 0; r < 4; ++r)
                ai4[r] = *reinterpret_cast<const float4*>(pi + r * D + ci);
            #pragma unroll
            for (int cc = 0; cc < 4; ++cc)
                aj4[cc] = *reinterpret_cast<const float4*>(pj + cc * D + cj);

            unsigned long long ailo[4], aihi[4], ajlo[4], ajhi[4];
            #pragma unroll
            for (int r = 0; r < 4; ++r) {
                ailo[r] = pack2(ai4[r].x, ai4[r].y);
                aihi[r] = pack2(ai4[r].z, ai4[r].w);
            }
            #pragma unroll
            for (int cc = 0; cc < 4; ++cc) {
                ajlo[cc] = pack2(aj4[cc].x, aj4[cc].y);
                ajhi[cc] = pack2(aj4[cc].z, aj4[cc].w);
            }
            #pragma unroll
            for (int r = 0; r < 4; ++r)
                #pragma unroll
                for (int cc = 0; cc < 4; ++cc) {
                    ffma2(acc[r][cc], ailo[r], ajlo[cc]);
                    ffma2(acc[r][cc], aihi[r], ajhi[cc]);
                }
        }
        #pragma unroll
        for (int r = 0; r < 4; ++r)
            #pragma unroll
            for (int cc = 0; cc < 4; ++cc) {
                float lo, hi;
                unpack2(acc[r][cc], lo, hi);
                val[r][cc] = lo + hi;
            }
    }
    __syncwarp();   // this warp's tile reads complete; its columns are scratch

    // ---- Warp dh==1 deposits 448 partials into its own dead columns ----
    if (valid && lane < 28 && dh == 1) {
        #pragma unroll
        for (int r = 0; r < 4; ++r)
            #pragma unroll
            for (int cc = 0; cc < 4; ++cc) {
                const int w = (r * 4 + cc) * 28 + lane;
                smb[(w >> 6) * D + HALF + (w & 63)] = val[r][cc];
            }
    }
    __syncthreads();

    // ---- Warp dh==0 reduces, scatters triu into its own dead columns ----
    if (valid && lane < 28 && dh == 0) {
        #pragma unroll
        for (int r = 0; r < 4; ++r)
            #pragma unroll
            for (int cc = 0; cc < 4; ++cc) {
                const int w = (r * 4 + cc) * 28 + lane;
                val[r][cc] += smb[(w >> 6) * D + HALF + (w & 63)];
            }
        #pragma unroll
        for (int r = 0; r < 4; ++r) {
            const int i = 4 * ti + r;
            #pragma unroll
            for (int cc = 0; cc < 4; ++cc) {
                const int j = 4 * tj + cc;
                if (i < j && j < F) {
                    const int off = i * F - (i * (i + 1)) / 2 + (j - i - 1);
                    smb[(off >> 6) * D + (off & 63)] = val[r][cc];
                }
            }
        }
    }
    __syncwarp();

    // ---- Warp dh==0 stores the 351 triu floats coalesced ----
    if (valid && dh == 0) {
        float* outp = outb + FLAT;
        #pragma unroll
        for (int it = 0; it < (NPAIR + 31) / 32; ++it) {
            const int x = it * 32 + lane;
            if (x < NPAIR) outp[x] = smb[(x >> 6) * D + (x & 63)];
        }
    }
}

extern "C" void kernel_launch(void* const* d_in, const int* in_sizes, int n_in,
                              void* d_out, int out_size)
{
    const float* in = (const float*)d_in[0];
    float* out = (float*)d_out;
    const int batch = in_sizes[0] / FLAT;            // 16384
    const int grid = (batch + NBATCH - 1) / NBATCH;  // 5462
    fi_kernel<<<grid, THREADS>>>(in, out, batch);
}

// round 8
// speedup vs baseline: 1.0937x; 1.0937x over previous
#include <cuda_runtime.h>

// FeatureInteraction: B=16384, F=27, D=128
// out[b] = concat(embeddings[b].flatten() (3456), triu(E E^T, k=1) (351)) -> 3807 floats
//
// R8 (from R6 base): single batch of 54 independent LDG.32 in flight per lane
//     (M_max~55) instead of two drained rounds of 27; per-batch-pair named
//     barriers replace block-wide __syncthreads in the reduction. Compute:
//     d-split warps, XOR-swizzled LDS.128, packed fma.rn.f32x2 (unchanged).

static constexpr int F      = 27;
static constexpr int F_PAD  = 28;
static constexpr int D      = 128;
static constexpr int HALF   = 64;
static constexpr int FLAT   = F * D;              // 3456
static constexpr int NPAIR  = (F * (F - 1)) / 2;  // 351
static constexpr int ROWLEN = FLAT + NPAIR;       // 3807
static constexpr int NBATCH = 3;                  // batch elements per block
static constexpr int THREADS = NBATCH * 2 * 32;   // 192

__device__ __forceinline__ unsigned long long pack2(float x, float y) {
    unsigned long long r;
    asm("mov.b64 %0, {%1, %2};" : "=l"(r) : "f"(x), "f"(y));
    return r;
}
__device__ __forceinline__ void unpack2(unsigned long long v, float& x, float& y) {
    asm("mov.b64 {%0, %1}, %2;" : "=f"(x), "=f"(y) : "l"(v));
}
__device__ __forceinline__ void ffma2(unsigned long long& acc,
                                      unsigned long long a, unsigned long long b) {
    asm("fma.rn.f32x2 %0, %1, %2, %0;" : "+l"(acc) : "l"(a), "l"(b));
}

// Row f = words [f*128, f*128+128); 16B chunk c stored at slot c ^ (f>>2).
__device__ __forceinline__ int sm_word(int f, int d) {
    return f * D + ((((d >> 2) ^ (f >> 2)) << 2) | (d & 3));
}

__global__ void __launch_bounds__(THREADS, 4)
fi_kernel(const float* __restrict__ in, float* __restrict__ out, int batch)
{
    __shared__ float sm[NBATCH * F_PAD * D];      // 43008 B

    const int tid  = threadIdx.x;
    const int warp = tid >> 5;
    const int lane = tid & 31;
    const int nb   = warp >> 1;                   // batch slot in block
    const int dh   = warp & 1;                    // d-half owned by this warp
    const int b    = blockIdx.x * NBATCH + nb;
    const bool valid = b < batch;

    const float* __restrict__ inb  = in  + (size_t)b * FLAT;
    float*       __restrict__ outb = out + (size_t)b * ROWLEN;
    float* smb = sm + nb * (F_PAD * D);

    // ---- Stage this warp's d-half: 54 independent LDG.32 in flight ----
    if (valid) {
        smb[27 * D + dh * HALF + lane]      = 0.f;   // zero pad-row half
        smb[27 * D + dh * HALF + 32 + lane] = 0.f;

        const int d0 = dh * HALF + lane;             // this lane's two columns
        float v[2 * F];
        #pragma unroll
        for (int f = 0; f < F; ++f) v[f]     = inb[f * D + d0];
        #pragma unroll
        for (int f = 0; f < F; ++f) v[F + f] = inb[f * D + d0 + 32];
        #pragma unroll
        for (int f = 0; f < F; ++f) {
            smb[sm_word(f, d0)]      = v[f];
            smb[sm_word(f, d0 + 32)] = v[F + f];
        }
        #pragma unroll
        for (int f = 0; f < F; ++f) {
            outb[f * D + d0]      = v[f];
            outb[f * D + d0 + 32] = v[F + f];
        }
    }
    __syncwarp();

    // ---- Partial gram over this warp's d-half: lane<28 owns a 4x4 tile ----
    int ti = 0, tj = 0;
    float val[4][4];
    if (valid && lane < 28) {
        int l = lane, cnt = 7;
        while (l >= cnt) { l -= cnt; ++ti; --cnt; }
        tj = ti + l;

        unsigned long long acc[4][4];
        #pragma unroll
        for (int r = 0; r < 4; ++r)
            #pragma unroll
            for (int c = 0; c < 4; ++c) acc[r][c] = 0ull;

        const float* pi = smb + (4 * ti) * D;
        const float* pj = smb + (4 * tj) * D;

        const int c0 = dh * 16;
        #pragma unroll 2
        for (int c = c0; c < c0 + 16; ++c) {
            const int ci = (c ^ ti) << 2;
            const int cj = (c ^ tj) << 2;
            float4 ai4[4], aj4[4];
            #pragma unroll
            for (int r = 0; r < 4; ++r)
                ai4[r] = *reinterpret_cast<const float4*>(pi + r * D + ci);
            #pragma unroll
            for (int cc = 0; cc < 4; ++cc)
                aj4[cc] = *reinterpret_cast<const float4*>(pj + cc * D + cj);

            unsigned long long ailo[4], aihi[4], ajlo[4], ajhi[4];
            #pragma unroll
            for (int r = 0; r < 4; ++r) {
                ailo[r] = pack2(ai4[r].x, ai4[r].y);
                aihi[r] = pack2(ai4[r].z, ai4[r].w);
            }
            #pragma unroll
            for (int cc = 0; cc < 4; ++cc) {
                ajlo[cc] = pack2(aj4[cc].x, aj4[cc].y);
                ajhi[cc] = pack2(aj4[cc].z, aj4[cc].w);
            }
            #pragma unroll
            for (int r = 0; r < 4; ++r)
                #pragma unroll
                for (int cc = 0; cc < 4; ++cc) {
                    ffma2(acc[r][cc], ailo[r], ajlo[cc]);
                    ffma2(acc[r][cc], aihi[r], ajhi[cc]);
                }
        }
        #pragma unroll
        for (int r = 0; r < 4; ++r)
            #pragma unroll
            for (int cc = 0; cc < 4; ++cc) {
                float lo, hi;
                unpack2(acc[r][cc], lo, hi);
                val[r][cc] = lo + hi;
            }
    }
    __syncwarp();   // this warp's tile reads complete; its columns are scratch

    // ---- Warp dh==1 deposits 448 partials into its own dead columns ----
    if (valid && lane < 28 && dh == 1) {
        #pragma unroll
        for (int r = 0; r < 4; ++r)
            #pragma unroll
            for (int cc = 0; cc < 4; ++cc) {
                const int w = (r * 4 + cc) * 28 + lane;
                smb[(w >> 6) * D + HALF + (w & 63)] = val[r][cc];
            }
    }
    // Per-batch-pair named barrier (warps 2nb, 2nb+1 only; drains STS).
    if (valid)
        asm volatile("bar.sync %0, 64;" :: "r"(1 + nb) : "memory");

    // ---- Warp dh==0 reduces, scatters triu into its own dead columns ----
    if (valid && lane < 28 && dh == 0) {
        #pragma unroll
        for (int r = 0; r < 4; ++r)
            #pragma unroll
            for (int cc = 0; cc < 4; ++cc) {
                const int w = (r * 4 + cc) * 28 + lane;
                val[r][cc] += smb[(w >> 6) * D + HALF + (w & 63)];
            }
        #pragma unroll
        for (int r = 0; r < 4; ++r) {
            const int i = 4 * ti + r;
            #pragma unroll
            for (int cc = 0; cc < 4; ++cc) {
                const int j = 4 * tj + cc;
                if (i < j && j < F) {
                    const int off = i * F - (i * (i + 1)) / 2 + (j - i - 1);
                    smb[(off >> 6) * D + (off & 63)] = val[r][cc];
                }
            }
        }
    }
    __syncwarp();

    // ---- Warp dh==0 stores the 351 triu floats coalesced ----
    if (valid && dh == 0) {
        float* outp = outb + FLAT;
        #pragma unroll
        for (int it = 0; it < (NPAIR + 31) / 32; ++it) {
            const int x = it * 32 + lane;
            if (x < NPAIR) outp[x] = smb[(x >> 6) * D + (x & 63)];
        }
    }
}

extern "C" void kernel_launch(void* const* d_in, const int* in_sizes, int n_in,
                              void* d_out, int out_size)
{
    const float* in = (const float*)d_in[0];
    float* out = (float*)d_out;
    const int batch = in_sizes[0] / FLAT;            // 16384
    const int grid = (batch + NBATCH - 1) / NBATCH;  // 5462
    fi_kernel<<<grid, THREADS>>>(in, out, batch);
}

// round 9
// speedup vs baseline: 1.1063x; 1.0115x over previous
#include <cuda_runtime.h>

// FeatureInteraction: B=16384, F=27, D=128
// out[b] = concat(embeddings[b].flatten() (3456), triu(E E^T, k=1) (351)) -> 3807 floats
//
// R9: cp.async.cg (LDGSTS.128) stages gmem->smem directly (no staging
//     registers, pad row zero-filled for free) -> regs drop -> 7 blocks x 4
//     warps = 28 warps/SM (NBATCH=2, 28.7KB smem). Flat output via coalesced
//     smem readback. Compute: d-split warps, XOR-swizzled LDS.128, packed
//     fma.rn.f32x2. Per-batch named barriers.

static constexpr int F      = 27;
static constexpr int F_PAD  = 28;
static constexpr int D      = 128;
static constexpr int HALF   = 64;
static constexpr int FLAT   = F * D;              // 3456
static constexpr int NPAIR  = (F * (F - 1)) / 2;  // 351
static constexpr int ROWLEN = FLAT + NPAIR;       // 3807
static constexpr int NBATCH = 2;                  // batch elements per block
static constexpr int THREADS = NBATCH * 2 * 32;   // 128

__device__ __forceinline__ unsigned long long pack2(float x, float y) {
    unsigned long long r;
    asm("mov.b64 %0, {%1, %2};" : "=l"(r) : "f"(x), "f"(y));
    return r;
}
__device__ __forceinline__ void unpack2(unsigned long long v, float& x, float& y) {
    asm("mov.b64 {%0, %1}, %2;" : "=f"(x), "=f"(y) : "l"(v));
}
__device__ __forceinline__ void ffma2(unsigned long long& acc,
                                      unsigned long long a, unsigned long long b) {
    asm("fma.rn.f32x2 %0, %1, %2, %0;" : "+l"(acc) : "l"(a), "l"(b));
}
__device__ __forceinline__ void cp_async16(unsigned smem_addr, const void* gptr, int src_sz) {
    asm volatile("cp.async.cg.shared.global [%0], [%1], 16, %2;"
                 :: "r"(smem_addr), "l"(gptr), "r"(src_sz));
}

// Row f = words [f*128, f*128+128); 16B chunk c stored at slot c ^ (f>>2).
__device__ __forceinline__ int sm_word(int f, int d) {
    return f * D + ((((d >> 2) ^ (f >> 2)) << 2) | (d & 3));
}

__global__ void __launch_bounds__(THREADS, 7)
fi_kernel(const float* __restrict__ in, float* __restrict__ out, int batch)
{
    __shared__ float sm[NBATCH * F_PAD * D];      // 2*28*128*4 = 28672 B

    const int tid  = threadIdx.x;
    const int warp = tid >> 5;
    const int lane = tid & 31;
    const int nb   = warp >> 1;                   // batch slot in block
    const int dh   = warp & 1;                    // d-half owned by this warp
    const int b    = blockIdx.x * NBATCH + nb;
    const bool valid = b < batch;

    const float* __restrict__ inb  = in  + (size_t)b * FLAT;
    float*       __restrict__ outb = out + (size_t)b * ROWLEN;
    float* smb = sm + nb * (F_PAD * D);

    // ---- Stage this warp's d-half of all rows: 14 cp.async.cg 16B per lane
    // group. lane group g = lane>>4 handles rows of parity g; chunk cq is this
    // lane's 16B column. Row 27 (pad) zero-filled via src_size=0.
    if (valid) {
        const int g  = lane >> 4;
        const int cq = (lane & 15) + dh * 16;     // chunk 0..31 within row
        const float4* inb4 = reinterpret_cast<const float4*>(inb);
        #pragma unroll
        for (int k = 0; k < 14; ++k) {
            const int f = 2 * k + g;              // 0..27 (27 = pad)
            const unsigned saddr = (unsigned)__cvta_generic_to_shared(
                smb + f * D + ((cq ^ (f >> 2)) << 2));
            cp_async16(saddr, inb4 + f * 32 + cq, (f < F) ? 16 : 0);
        }
        asm volatile("cp.async.commit_group;");
        asm volatile("cp.async.wait_group 0;" ::: "memory");
    }
    __syncwarp();

    // ---- Flat output: coalesced smem readback -> coalesced STG.32 ----
    if (valid) {
        #pragma unroll 6
        for (int it = 0; it < F * 2; ++it) {      // 54 iters: this warp's d-half
            const int f = it >> 1;
            const int d = dh * HALF + ((it & 1) << 5) + lane;
            outb[f * D + d] = smb[sm_word(f, d)];
        }
    }

    // ---- Partial gram over this warp's d-half: lane<28 owns a 4x4 tile ----
    int ti = 0, tj = 0;
    float val[4][4];
    if (valid && lane < 28) {
        int l = lane, cnt = 7;
        while (l >= cnt) { l -= cnt; ++ti; --cnt; }
        tj = ti + l;

        unsigned long long acc[4][4];
        #pragma unroll
        for (int r = 0; r < 4; ++r)
            #pragma unroll
            for (int c = 0; c < 4; ++c) acc[r][c] = 0ull;

        const float* pi = smb + (4 * ti) * D;
        const float* pj = smb + (4 * tj) * D;

        const int c0 = dh * 16;
        #pragma unroll 2
        for (int c = c0; c < c0 + 16; ++c) {
            const int ci = (c ^ ti) << 2;
            const int cj = (c ^ tj) << 2;
            float4 ai4[4], aj4[4];
            #pragma unroll
            for (int r = 0; r < 4; ++r)
                ai4[r] = *reinterpret_cast<const float4*>(pi + r * D + ci);
            #pragma unroll
            for (int cc = 0; cc < 4; ++cc)
                aj4[cc] = *reinterpret_cast<const float4*>(pj + cc * D + cj);

            unsigned long long ailo[4], aihi[4], ajlo[4], ajhi[4];
            #pragma unroll
            for (int r = 0; r < 4; ++r) {
                ailo[r] = pack2(ai4[r].x, ai4[r].y);
                aihi[r] = pack2(ai4[r].z, ai4[r].w);
            }
            #pragma unroll
            for (int cc = 0; cc < 4; ++cc) {
                ajlo[cc] = pack2(aj4[cc].x, aj4[cc].y);
                ajhi[cc] = pack2(aj4[cc].z, aj4[cc].w);
            }
            #pragma unroll
            for (int r = 0; r < 4; ++r)
                #pragma unroll
                for (int cc = 0; cc < 4; ++cc) {
                    ffma2(acc[r][cc], ailo[r], ajlo[cc]);
                    ffma2(acc[r][cc], aihi[r], ajhi[cc]);
                }
        }
        #pragma unroll
        for (int r = 0; r < 4; ++r)
            #pragma unroll
            for (int cc = 0; cc < 4; ++cc) {
                float lo, hi;
                unpack2(acc[r][cc], lo, hi);
                val[r][cc] = lo + hi;
            }
    }
    __syncwarp();   // this warp's tile reads complete; its columns are scratch

    // ---- Warp dh==1 deposits 448 partials into its own dead columns ----
    if (valid && lane < 28 && dh == 1) {
        #pragma unroll
        for (int r = 0; r < 4; ++r)
            #pragma unroll
            for (int cc = 0; cc < 4; ++cc) {
                const int w = (r * 4 + cc) * 28 + lane;
                smb[(w >> 6) * D + HALF + (w & 63)] = val[r][cc];
            }
    }
    // Per-batch named barrier (warps 2nb, 2nb+1 only; drains STS).
    if (valid)
        asm volatile("bar.sync %0, 64;" :: "r"(1 + nb) : "memory");

    // ---- Warp dh==0 reduces, scatters triu into its own dead columns ----
    if (valid && lane < 28 && dh == 0) {
        #pragma unroll
        for (int r = 0; r < 4; ++r)
            #pragma unroll
            for (int cc = 0; cc < 4; ++cc) {
                const int w = (r * 4 + cc) * 28 + lane;
                val[r][cc] += smb[(w >> 6) * D + HALF + (w & 63)];
            }
        #pragma unroll
        for (int r = 0; r < 4; ++r) {
            const int i = 4 * ti + r;
            #pragma unroll
            for (int cc = 0; cc < 4; ++cc) {
                const int j = 4 * tj + cc;
                if (i < j && j < F) {
                    const int off = i * F - (i * (i + 1)) / 2 + (j - i - 1);
                    smb[(off >> 6) * D + (off & 63)] = val[r][cc];
                }
            }
        }
    }
    __syncwarp();

    // ---- Warp dh==0 stores the 351 triu floats coalesced ----
    if (valid && dh == 0) {
        float* outp = outb + FLAT;
        #pragma unroll
        for (int it = 0; it < (NPAIR + 31) / 32; ++it) {
            const int x = it * 32 + lane;
            if (x < NPAIR) outp[x] = smb[(x >> 6) * D + (x & 63)];
        }
    }
}

extern "C" void kernel_launch(void* const* d_in, const int* in_sizes, int n_in,
                              void* d_out, int out_size)
{
    const float* in = (const float*)d_in[0];
    float* out = (float*)d_out;
    const int batch = in_sizes[0] / FLAT;            // 16384
    const int grid = (batch + NBATCH - 1) / NBATCH;  // 8192
    fi_kernel<<<grid, THREADS>>>(in, out, batch);
}